// round 1
// baseline (speedup 1.0000x reference)
#include <cuda_runtime.h>
#include <stdint.h>

#define EPS 1e-5f

// ---------------- scratch (static device globals; no allocation) ------------
// Packed sign bits of stage-1 output: per (b,h) 760 bits (p = w*40 + c1) in 24 u32.
__device__ uint32_t g_A[256 * 600 * 24];     // 14.7 MB, L2-resident
__device__ uint32_t g_W2[40 * 24];           // conv2 weight signs, same bit order
__device__ uint32_t g_FC1[80 * 49];          // fc1 weight signs (1560 bits -> 49 u32)
__device__ uint32_t g_FC2[2 * 3];            // fc2 weight signs (80 bits -> 3 u32)
__device__ uint32_t g_PB[256 * 49];          // pooled sign bits per batch (1560 bits)

// ---------------- kernel W: pack binary weights -----------------------------
__global__ void kw_pack(const float* __restrict__ w2,
                        const float* __restrict__ fc1,
                        const float* __restrict__ fc2) {
    int tid = threadIdx.x;
    // conv2 weights: bit p = kw*40 + c1 of row c2
    for (int idx = tid; idx < 40 * 24; idx += blockDim.x) {
        int c2 = idx / 24, k = idx % 24;
        uint32_t word = 0;
        #pragma unroll
        for (int j = 0; j < 32; j++) {
            int p = 32 * k + j;
            if (p < 760) {
                int kw = p / 40, c1 = p % 40;
                if (w2[(c2 * 40 + c1) * 19 + kw] > 0.f) word |= (1u << j);
            }
        }
        g_W2[idx] = word;
    }
    // fc1 weights: bit i of row o
    for (int idx = tid; idx < 80 * 49; idx += blockDim.x) {
        int o = idx / 49, k = idx % 49;
        uint32_t word = 0;
        #pragma unroll
        for (int j = 0; j < 32; j++) {
            int i = 32 * k + j;
            if (i < 1560 && fc1[o * 1560 + i] > 0.f) word |= (1u << j);
        }
        g_FC1[idx] = word;
    }
    // fc2 weights
    for (int idx = tid; idx < 6; idx += blockDim.x) {
        int o = idx / 3, k = idx % 3;
        uint32_t word = 0;
        #pragma unroll
        for (int j = 0; j < 32; j++) {
            int i = 32 * k + j;
            if (i < 80 && fc2[o * 80 + i] > 0.f) word |= (1u << j);
        }
        g_FC2[idx] = word;
    }
}

// ---------------- kernel A: conv1 (29x1, pad 14) + BN1 + sign + bitpack -----
// Block: (chunk of 60 h-rows, batch b). 128 threads; 114 active: w = tid%19,
// slot = tid/19 (6 slots x 10 h each). Thread keeps 38-float x window in regs,
// loops all 40 channels (weights broadcast from shared) -> LDS:FFMA ~ 1:8.
__global__ __launch_bounds__(128) void ka_conv1(
    const float* __restrict__ x, const float* __restrict__ w1,
    const float* __restrict__ bg, const float* __restrict__ bbv,
    const float* __restrict__ bm, const float* __restrict__ bv) {
    __shared__ float xs[88 * 19];
    __shared__ float ws[40 * 29];
    __shared__ float scs[40], sbs[40];
    __shared__ uint32_t outw[60 * 24];

    int tid = threadIdx.x;
    int chunk = blockIdx.x;          // 0..9
    int b = blockIdx.y;              // 0..255
    int h0 = chunk * 60;

    for (int idx = tid; idx < 88 * 19; idx += 128) {
        int r = idx / 19, c = idx % 19;
        int gh = h0 - 14 + r;
        xs[idx] = (gh >= 0 && gh < 600) ? x[(b * 600 + gh) * 19 + c] : 0.f;
    }
    for (int idx = tid; idx < 40 * 29; idx += 128)
        ws[idx] = (w1[idx] > 0.f) ? 1.f : -1.f;
    if (tid < 40) {
        float sc = bg[tid] / sqrtf(bv[tid] + EPS);
        scs[tid] = sc;
        sbs[tid] = __fsub_rn(bbv[tid], __fmul_rn(bm[tid], sc));  // b - m*scale (no FMA)
    }
    for (int idx = tid; idx < 60 * 24; idx += 128) outw[idx] = 0;
    __syncthreads();

    if (tid < 114) {
        int w = tid % 19;
        int slot = tid / 19;                 // 0..5, each covers 10 h rows
        float xr[38];
        #pragma unroll
        for (int i = 0; i < 38; i++) xr[i] = xs[(slot * 10 + i) * 19 + w];

        unsigned long long mask[10];
        #pragma unroll
        for (int j = 0; j < 10; j++) mask[j] = 0ull;

        for (int c1 = 0; c1 < 40; c1++) {
            float acc[10];
            #pragma unroll
            for (int j = 0; j < 10; j++) acc[j] = 0.f;
            #pragma unroll
            for (int t = 0; t < 29; t++) {       // sequential tap order (matches direct conv)
                float s = ws[c1 * 29 + t];
                #pragma unroll
                for (int j = 0; j < 10; j++) acc[j] = fmaf(s, xr[t + j], acc[j]);
            }
            float sc = scs[c1], sb = sbs[c1];
            #pragma unroll
            for (int j = 0; j < 10; j++) {
                float y = __fadd_rn(__fmul_rn(acc[j], sc), sb);  // separate mul+add (XLA-style)
                if (y > 0.f) mask[j] |= (1ull << c1);
            }
        }
        // pack: bits [w*40, w*40+40) -> spans exactly 2 u32 words (w*40 % 32 in {0,8,16,24})
        int b0 = w * 40;
        int wi = b0 >> 5, sh = b0 & 31;
        #pragma unroll
        for (int j = 0; j < 10; j++) {
            int row = slot * 10 + j;
            atomicOr(&outw[row * 24 + wi], (uint32_t)(mask[j] << sh));
            atomicOr(&outw[row * 24 + wi + 1], (uint32_t)(mask[j] >> (32 - sh)));
        }
    }
    __syncthreads();
    for (int idx = tid; idx < 60 * 24; idx += 128) {
        int row = idx / 24, k = idx % 24;
        g_A[((b * 600) + h0 + row) * 24 + k] = outw[idx];
    }
}

// ---------------- kernel B: binary conv2 + BN2 + PReLU + avgpool + sign -----
// Block per batch b. A-row block staged in shared (stride 25 -> conflict-free).
// Each warp handles 5 of 40 output channels; lanes over h; pool windows summed
// sequentially (ascending) to mirror reduce_window.
__global__ void kb_conv2(const float* __restrict__ bg, const float* __restrict__ bbv,
                         const float* __restrict__ bm, const float* __restrict__ bv,
                         const float* __restrict__ a2) {
    extern __shared__ uint32_t sm[];
    uint32_t* sa = sm;                              // 600*25
    uint32_t* sw = sm + 600 * 25;                   // 40*24
    float* ssc = (float*)(sw + 40 * 24);            // 40
    float* ssb = ssc + 40;                          // 40
    float* pbuf = ssb + 40;                         // 8*600
    uint32_t* outm = (uint32_t*)(pbuf + 8 * 600);   // 49

    int tid = threadIdx.x;
    int b = blockIdx.x;
    int lane = tid & 31, wp = tid >> 5;

    for (int idx = tid; idx < 600 * 24; idx += 256)
        sa[(idx / 24) * 25 + (idx % 24)] = g_A[b * 600 * 24 + idx];
    for (int idx = tid; idx < 40 * 24; idx += 256) sw[idx] = g_W2[idx];
    if (tid < 40) {
        float sc = bg[tid] / sqrtf(bv[tid] + EPS);
        ssc[tid] = sc;
        ssb[tid] = __fsub_rn(bbv[tid], __fmul_rn(bm[tid], sc));
    }
    if (tid < 49) outm[tid] = 0;
    float av = a2[0];
    __syncthreads();

    for (int cc = 0; cc < 5; cc++) {
        int c2 = wp * 5 + cc;
        uint32_t wreg[24];
        #pragma unroll
        for (int k = 0; k < 24; k++) wreg[k] = sw[c2 * 24 + k];
        float sc = ssc[c2], sb = ssb[c2];

        for (int h = lane; h < 600; h += 32) {
            int cnt = 0;
            #pragma unroll
            for (int k = 0; k < 24; k++) cnt += __popc(sa[h * 25 + k] ^ wreg[k]);
            float dot = (float)(760 - 2 * cnt);                // exact integer
            float y = __fadd_rn(__fmul_rn(dot, sc), sb);
            float p = (y >= 0.f) ? y : __fmul_rn(av, y);       // PReLU
            pbuf[wp * 600 + h] = p;
        }
        __syncwarp();

        // 39 pool windows [15j, 15j+30), summed sequentially
        const float* pw = pbuf + wp * 600;
        float pooled = 0.f;
        int j = lane;                                          // j = 0..31
        #pragma unroll 1
        for (int i = 0; i < 30; i++) pooled = __fadd_rn(pooled, pw[15 * j + i]);
        uint32_t bl = __ballot_sync(0xFFFFFFFFu, pooled > 0.f);

        float pooled2 = 0.f;
        if (lane < 7) {                                        // j = 32..38
            int j2 = 32 + lane;
            #pragma unroll 1
            for (int i = 0; i < 30; i++) pooled2 = __fadd_rn(pooled2, pw[15 * j2 + i]);
        }
        uint32_t bh = __ballot_sync(0xFFFFFFFFu, (lane < 7) && (pooled2 > 0.f));

        if (lane == 0) {
            unsigned long long mm = (unsigned long long)bl | ((unsigned long long)bh << 32);
            int base = c2 * 39;                                // flat bit index c2*39 + j
            int bi = base >> 5, sh = base & 31;
            unsigned __int128 big = ((unsigned __int128)mm) << sh;
            uint32_t w0 = (uint32_t)big;
            uint32_t w1 = (uint32_t)(big >> 32);
            uint32_t w2 = (uint32_t)(big >> 64);
            atomicOr(&outm[bi], w0);
            if (w1) atomicOr(&outm[bi + 1], w1);
            if (w2) atomicOr(&outm[bi + 2], w2);
        }
        __syncwarp();
    }
    __syncthreads();
    if (tid < 49) g_PB[b * 49 + tid] = outm[tid];
}

// ---------------- kernel C: binary FC1 + BN3 + sign + binary FC2 ------------
__global__ void kc_fc(const float* __restrict__ g3, const float* __restrict__ b3,
                      const float* __restrict__ m3, const float* __restrict__ v3,
                      float* __restrict__ out) {
    __shared__ uint32_t pb[49];
    __shared__ uint32_t fw[80 * 49];
    __shared__ uint32_t hb[3];
    int tid = threadIdx.x;
    int b = blockIdx.x;

    if (tid < 49) pb[tid] = g_PB[b * 49 + tid];
    for (int idx = tid; idx < 80 * 49; idx += 128) fw[idx] = g_FC1[idx];
    __syncthreads();

    bool bit = false;
    if (tid < 80) {
        int cnt = 0;
        #pragma unroll
        for (int k = 0; k < 49; k++) cnt += __popc(pb[k] ^ fw[tid * 49 + k]);
        int dot = 1560 - 2 * cnt;                               // exact integer
        float sc = g3[tid] / sqrtf(v3[tid] + EPS);
        float sb = __fsub_rn(b3[tid], __fmul_rn(m3[tid], sc));
        float y = __fadd_rn(__fmul_rn((float)dot, sc), sb);
        bit = (y > 0.f);                                        // sign(prelu(y)) = sign(y)
    }
    uint32_t bl = __ballot_sync(0xFFFFFFFFu, bit);
    if ((tid & 31) == 0 && tid < 96) hb[tid >> 5] = bl;
    __syncthreads();

    if (tid < 2) {
        int cnt = 0;
        #pragma unroll
        for (int k = 0; k < 3; k++) cnt += __popc(hb[k] ^ g_FC2[tid * 3 + k]);
        int dot = 80 - 2 * cnt;                                 // exact integer
        out[b * 2 + tid] = (float)dot;
    }
}

// ---------------- launch -----------------------------------------------------
extern "C" void kernel_launch(void* const* d_in, const int* in_sizes, int n_in,
                              void* d_out, int out_size) {
    const float* x    = (const float*)d_in[0];
    const float* w1   = (const float*)d_in[1];
    const float* bn1g = (const float*)d_in[2];
    const float* bn1b = (const float*)d_in[3];
    const float* bn1m = (const float*)d_in[4];
    const float* bn1v = (const float*)d_in[5];
    // d_in[6] = a1 (sign-invariant, unused)
    const float* w2   = (const float*)d_in[7];
    const float* bn2g = (const float*)d_in[8];
    const float* bn2b = (const float*)d_in[9];
    const float* bn2m = (const float*)d_in[10];
    const float* bn2v = (const float*)d_in[11];
    const float* a2   = (const float*)d_in[12];
    const float* fc1  = (const float*)d_in[13];
    const float* bn3g = (const float*)d_in[14];
    const float* bn3b = (const float*)d_in[15];
    const float* bn3m = (const float*)d_in[16];
    const float* bn3v = (const float*)d_in[17];
    // d_in[18] = a3 (sign-invariant, unused)
    const float* fc2  = (const float*)d_in[19];
    float* out = (float*)d_out;

    kw_pack<<<1, 256>>>(w2, fc1, fc2);

    dim3 gA(10, 256);
    ka_conv1<<<gA, 128>>>(x, w1, bn1g, bn1b, bn1m, bn1v);

    size_t smemB = (size_t)(600 * 25 + 40 * 24 + 40 + 40 + 8 * 600 + 49) * 4;
    cudaFuncSetAttribute(kb_conv2, cudaFuncAttributeMaxDynamicSharedMemorySize, (int)smemB);
    kb_conv2<<<256, 256, smemB>>>(bn2g, bn2b, bn2m, bn2v, a2);

    kc_fc<<<256, 128>>>(bn3g, bn3b, bn3m, bn3v, out);
}

// round 2
// speedup vs baseline: 1.1289x; 1.1289x over previous
#include <cuda_runtime.h>
#include <stdint.h>

#define EPS 1e-5f

typedef unsigned long long ull;

// ---------------- scratch (static device globals; no allocation) ------------
__device__ uint32_t g_A[256 * 600 * 24];     // stage-1 sign bits: (b,h) -> 760 bits (p = w*40 + c1)
__device__ uint32_t g_W2[40 * 24];           // conv2 weight signs, same bit order
__device__ uint32_t g_FC1[80 * 49];          // fc1 weight signs (1560 bits)
__device__ uint32_t g_FC2[2 * 3];            // fc2 weight signs (80 bits)

// ---------------- f32x2 helpers ----------------------------------------------
__device__ __forceinline__ ull pk2(float lo, float hi) {
    ull r; asm("mov.b64 %0, {%1,%2};" : "=l"(r) : "f"(lo), "f"(hi)); return r;
}
__device__ __forceinline__ ull fma2(ull a, ull b, ull c) {
    ull d; asm("fma.rn.f32x2 %0, %1, %2, %3;" : "=l"(d) : "l"(a), "l"(b), "l"(c)); return d;
}
__device__ __forceinline__ void upk2(ull v, float& lo, float& hi) {
    asm("mov.b64 {%0,%1}, %2;" : "=f"(lo), "=f"(hi) : "l"(v));
}

// ---------------- kernel W: pack binary weights -----------------------------
__global__ void kw_pack(const float* __restrict__ w2,
                        const float* __restrict__ fc1,
                        const float* __restrict__ fc2) {
    int tid = threadIdx.x;
    for (int idx = tid; idx < 40 * 24; idx += blockDim.x) {
        int c2 = idx / 24, k = idx % 24;
        uint32_t word = 0;
        #pragma unroll
        for (int j = 0; j < 32; j++) {
            int p = 32 * k + j;
            if (p < 760) {
                int kw = p / 40, c1 = p % 40;
                if (w2[(c2 * 40 + c1) * 19 + kw] > 0.f) word |= (1u << j);
            }
        }
        g_W2[idx] = word;
    }
    for (int idx = tid; idx < 80 * 49; idx += blockDim.x) {
        int o = idx / 49, k = idx % 49;
        uint32_t word = 0;
        #pragma unroll
        for (int j = 0; j < 32; j++) {
            int i = 32 * k + j;
            if (i < 1560 && fc1[o * 1560 + i] > 0.f) word |= (1u << j);
        }
        g_FC1[idx] = word;
    }
    for (int idx = tid; idx < 6; idx += blockDim.x) {
        int o = idx / 3, k = idx % 3;
        uint32_t word = 0;
        #pragma unroll
        for (int j = 0; j < 32; j++) {
            int i = 32 * k + j;
            if (i < 80 && fc2[o * 80 + i] > 0.f) word |= (1u << j);
        }
        g_FC2[idx] = word;
    }
}

// ---------------- kernel A: conv1 + BN1 + sign + bitpack, f32x2 -------------
// 96 threads, 95 active: w = tid%19, slot = tid/19 (5 slots x 12 h rows = 60).
// Channels processed in pairs (c1, c1+20) packed into f32x2 lanes; per-lane
// accumulation is t-ascending rn-FMA, bit-identical to the scalar version.
__global__ __launch_bounds__(96, 4) void ka_conv1(
    const float* __restrict__ x, const float* __restrict__ w1,
    const float* __restrict__ bg, const float* __restrict__ bbv,
    const float* __restrict__ bm, const float* __restrict__ bv) {
    __shared__ float xs[88 * 19];
    __shared__ ull wsp[20 * 29];            // packed sign pairs (c1, c1+20)
    __shared__ float scs[40], sbs[40];
    __shared__ uint32_t outw[60 * 24];

    int tid = threadIdx.x;
    int h0 = blockIdx.x * 60;
    int b = blockIdx.y;

    for (int idx = tid; idx < 88 * 19; idx += 96) {
        int r = idx / 19, c = idx % 19;
        int gh = h0 - 14 + r;
        xs[idx] = (gh >= 0 && gh < 600) ? x[(b * 600 + gh) * 19 + c] : 0.f;
    }
    for (int idx = tid; idx < 20 * 29; idx += 96) {
        int p = idx / 29, t = idx % 29;
        float lo = (w1[p * 29 + t] > 0.f) ? 1.f : -1.f;
        float hi = (w1[(p + 20) * 29 + t] > 0.f) ? 1.f : -1.f;
        wsp[idx] = pk2(lo, hi);
    }
    if (tid < 40) {
        float sc = bg[tid] / sqrtf(bv[tid] + EPS);
        scs[tid] = sc;
        sbs[tid] = __fsub_rn(bbv[tid], __fmul_rn(bm[tid], sc));
    }
    for (int idx = tid; idx < 60 * 24; idx += 96) outw[idx] = 0;
    __syncthreads();

    if (tid < 95) {
        int w = tid % 19;
        int slot = tid / 19;                 // 0..4, 12 h rows each
        ull xd[40];
        #pragma unroll
        for (int i = 0; i < 40; i++) {
            float v = xs[(slot * 12 + i) * 19 + w];
            xd[i] = pk2(v, v);
        }

        ull mask[12];
        #pragma unroll
        for (int j = 0; j < 12; j++) mask[j] = 0ull;

        for (int pair = 0; pair < 20; pair++) {
            ull acc[12];
            #pragma unroll
            for (int j = 0; j < 12; j++) acc[j] = 0ull;   // (+0.f, +0.f)
            #pragma unroll
            for (int t = 0; t < 29; t++) {                // sequential tap order
                ull s2 = wsp[pair * 29 + t];
                #pragma unroll
                for (int j = 0; j < 12; j++) acc[j] = fma2(s2, xd[t + j], acc[j]);
            }
            float sclo = scs[pair], sblo = sbs[pair];
            float schi = scs[pair + 20], sbhi = sbs[pair + 20];
            #pragma unroll
            for (int j = 0; j < 12; j++) {
                float alo, ahi;
                upk2(acc[j], alo, ahi);
                float ylo = __fadd_rn(__fmul_rn(alo, sclo), sblo);
                float yhi = __fadd_rn(__fmul_rn(ahi, schi), sbhi);
                if (ylo > 0.f) mask[j] |= (1ull << pair);
                if (yhi > 0.f) mask[j] |= (1ull << (pair + 20));
            }
        }
        // pack: bits [w*40, w*40+40) span exactly 2 u32 words (w*40 % 32 in {0,8,16,24})
        int b0 = w * 40;
        int wi = b0 >> 5, sh = b0 & 31;
        #pragma unroll
        for (int j = 0; j < 12; j++) {
            int row = slot * 12 + j;
            atomicOr(&outw[row * 24 + wi], (uint32_t)(mask[j] << sh));
            atomicOr(&outw[row * 24 + wi + 1], (uint32_t)(mask[j] >> (32 - sh)));
        }
    }
    __syncthreads();
    for (int idx = tid; idx < 60 * 24; idx += 96) {
        int row = idx / 24, k = idx % 24;
        g_A[((b * 600) + h0 + row) * 24 + k] = outw[idx];
    }
}

// ---------------- kernel B: binary conv2 + BN2 + PReLU + pool + FC1/BN3/FC2 -
// Block per batch. Thread owns h rows: loads the 760-bit row ONCE (12 u64 from
// L2-resident g_A), loops channels with broadcast weight LDS. Two 20-channel
// passes over pbuf. Ends with the fused fully-connected head.
__global__ __launch_bounds__(256) void kb_conv2(
    const float* __restrict__ bg, const float* __restrict__ bbv,
    const float* __restrict__ bm, const float* __restrict__ bv,
    const float* __restrict__ a2,
    const float* __restrict__ g3, const float* __restrict__ b3,
    const float* __restrict__ m3, const float* __restrict__ v3,
    float* __restrict__ out) {
    extern __shared__ uint32_t sm[];
    float*    pbuf = (float*)sm;                  // 20*600 floats   (48000 B)
    uint32_t* w2p  = sm + 12000;                  // 40*24 u32       (3840 B, 8B-aligned)
    uint32_t* fcw  = w2p + 40 * 24;               // 80*49 u32       (15680 B)
    float*    ssc  = (float*)(fcw + 80 * 49);     // 40
    float*    ssb  = ssc + 40;                    // 40
    float*    sc3  = ssb + 40;                    // 80
    float*    sb3  = sc3 + 80;                    // 80
    uint32_t* outm = (uint32_t*)(sb3 + 80);       // 49
    uint32_t* hb   = outm + 52;                   // 3 (8B-aligned region)

    int tid = threadIdx.x;
    int b = blockIdx.x;

    for (int idx = tid; idx < 40 * 24; idx += 256) w2p[idx] = g_W2[idx];
    for (int idx = tid; idx < 80 * 49; idx += 256) fcw[idx] = g_FC1[idx];
    if (tid < 40) {
        float sc = bg[tid] / sqrtf(bv[tid] + EPS);
        ssc[tid] = sc;
        ssb[tid] = __fsub_rn(bbv[tid], __fmul_rn(bm[tid], sc));
    }
    if (tid < 80) {
        float sc = g3[tid] / sqrtf(v3[tid] + EPS);
        sc3[tid] = sc;
        sb3[tid] = __fsub_rn(b3[tid], __fmul_rn(m3[tid], sc));
    }
    if (tid < 52) outm[tid] = 0;
    float av = a2[0];
    __syncthreads();

    const ull* arow_base = (const ull*)(g_A + b * 600 * 24);
    const ull* w2p64 = (const ull*)w2p;

    #pragma unroll
    for (int p = 0; p < 2; p++) {
        for (int h = tid; h < 600; h += 256) {
            ull ab[12];
            const ull* ar = arow_base + h * 12;
            #pragma unroll
            for (int k = 0; k < 12; k++) ab[k] = __ldg(&ar[k]);
            #pragma unroll 4
            for (int c = 0; c < 20; c++) {
                int c2 = p * 20 + c;
                const ull* wr = w2p64 + c2 * 12;
                int cnt = 0;
                #pragma unroll
                for (int k = 0; k < 12; k++) cnt += __popcll(ab[k] ^ wr[k]);
                float dot = (float)(760 - 2 * cnt);                 // exact integer
                float y = __fadd_rn(__fmul_rn(dot, ssc[c2]), ssb[c2]);
                pbuf[c * 600 + h] = (y >= 0.f) ? y : __fmul_rn(av, y);
            }
        }
        __syncthreads();
        // pooling: 20 channels x 39 windows, each summed ascending
        for (int idx = tid; idx < 20 * 39; idx += 256) {
            int c = idx / 39, j = idx % 39;
            const float* pw = pbuf + c * 600 + 15 * j;
            float s = 0.f;
            #pragma unroll 1
            for (int i = 0; i < 30; i++) s = __fadd_rn(s, pw[i]);
            if (s > 0.f) {
                int bit = (p * 20 + c) * 39 + j;                    // flat index in 1560
                atomicOr(&outm[bit >> 5], 1u << (bit & 31));
            }
        }
        __syncthreads();
    }

    // fused FC1 + BN3 + sign + FC2
    bool bit = false;
    if (tid < 80) {
        int cnt = 0;
        #pragma unroll
        for (int k = 0; k < 49; k++) cnt += __popc(outm[k] ^ fcw[tid * 49 + k]);
        int dot = 1560 - 2 * cnt;                                   // exact integer
        float y = __fadd_rn(__fmul_rn((float)dot, sc3[tid]), sb3[tid]);
        bit = (y > 0.f);                                            // sign(prelu(y)) = sign(y)
    }
    uint32_t bl = __ballot_sync(0xFFFFFFFFu, bit);
    if ((tid & 31) == 0 && tid < 96) hb[tid >> 5] = bl;
    __syncthreads();

    if (tid < 2) {
        int cnt = 0;
        #pragma unroll
        for (int k = 0; k < 3; k++) cnt += __popc(hb[k] ^ g_FC2[tid * 3 + k]);
        out[b * 2 + tid] = (float)(80 - 2 * cnt);                   // exact integer
    }
}

// ---------------- launch -----------------------------------------------------
extern "C" void kernel_launch(void* const* d_in, const int* in_sizes, int n_in,
                              void* d_out, int out_size) {
    const float* x    = (const float*)d_in[0];
    const float* w1   = (const float*)d_in[1];
    const float* bn1g = (const float*)d_in[2];
    const float* bn1b = (const float*)d_in[3];
    const float* bn1m = (const float*)d_in[4];
    const float* bn1v = (const float*)d_in[5];
    const float* w2   = (const float*)d_in[7];
    const float* bn2g = (const float*)d_in[8];
    const float* bn2b = (const float*)d_in[9];
    const float* bn2m = (const float*)d_in[10];
    const float* bn2v = (const float*)d_in[11];
    const float* a2   = (const float*)d_in[12];
    const float* fc1  = (const float*)d_in[13];
    const float* bn3g = (const float*)d_in[14];
    const float* bn3b = (const float*)d_in[15];
    const float* bn3m = (const float*)d_in[16];
    const float* bn3v = (const float*)d_in[17];
    const float* fc2  = (const float*)d_in[19];
    float* out = (float*)d_out;

    kw_pack<<<1, 256>>>(w2, fc1, fc2);

    dim3 gA(10, 256);
    ka_conv1<<<gA, 96>>>(x, w1, bn1g, bn1b, bn1m, bn1v);

    size_t smemB = (size_t)(12000 + 40 * 24 + 80 * 49 + 40 + 40 + 80 + 80 + 52 + 4) * 4;
    cudaFuncSetAttribute(kb_conv2, cudaFuncAttributeMaxDynamicSharedMemorySize, (int)smemB);
    kb_conv2<<<256, 256, smemB>>>(bn2g, bn2b, bn2m, bn2v, a2,
                                  bn3g, bn3b, bn3m, bn3v, out);
}

// round 3
// speedup vs baseline: 1.5172x; 1.3440x over previous
#include <cuda_runtime.h>
#include <stdint.h>

#define EPS 1e-5f

typedef unsigned long long ull;

// ---------------- scratch (static device globals; no allocation) ------------
__device__ uint32_t g_A[256 * 600 * 24];     // stage-1 sign bits: (b,h) -> 760 bits (p = w*40 + c1)
__device__ uint32_t g_W2[40 * 24];           // conv2 weight signs, same bit order
__device__ uint32_t g_FC1[80 * 49];          // fc1 weight signs (1560 bits)
__device__ uint32_t g_FC2[2 * 3];            // fc2 weight signs (80 bits)

// ---------------- f32x2 helpers ----------------------------------------------
__device__ __forceinline__ ull pk2(float lo, float hi) {
    ull r; asm("mov.b64 %0, {%1,%2};" : "=l"(r) : "f"(lo), "f"(hi)); return r;
}
__device__ __forceinline__ ull fma2(ull a, ull b, ull c) {
    ull d; asm("fma.rn.f32x2 %0, %1, %2, %3;" : "=l"(d) : "l"(a), "l"(b), "l"(c)); return d;
}
__device__ __forceinline__ void upk2(ull v, float& lo, float& hi) {
    asm("mov.b64 {%0,%1}, %2;" : "=f"(lo), "=f"(hi) : "l"(v));
}

// ---------------- kernel W: pack binary weights (warp-ballot, full chip) ----
// One warp per output u32 word. Lane j supplies bit j via ballot.
// Word layout identical to previous rounds (bit-exact scratch format).
__global__ void kw_pack(const float* __restrict__ w2,
                        const float* __restrict__ fc1,
                        const float* __restrict__ fc2) {
    int gwid = (blockIdx.x * blockDim.x + threadIdx.x) >> 5;
    int lane = threadIdx.x & 31;

    if (gwid < 960) {                        // conv2: 40 rows x 24 words
        int c2 = gwid / 24, k = gwid % 24;
        int p = 32 * k + lane;               // bit p = kw*40 + c1
        bool bit = false;
        if (p < 760) {
            int kw = p / 40, c1 = p % 40;
            bit = w2[(c2 * 40 + c1) * 19 + kw] > 0.f;
        }
        uint32_t word = __ballot_sync(0xFFFFFFFFu, bit);
        if (lane == 0) g_W2[gwid] = word;
    } else if (gwid < 960 + 3920) {          // fc1: 80 rows x 49 words
        int i = gwid - 960;
        int o = i / 49, k = i % 49;
        int idx = 32 * k + lane;
        bool bit = (idx < 1560) && (fc1[o * 1560 + idx] > 0.f);
        uint32_t word = __ballot_sync(0xFFFFFFFFu, bit);
        if (lane == 0) g_FC1[i] = word;
    } else if (gwid < 960 + 3920 + 6) {      // fc2: 2 rows x 3 words
        int i = gwid - (960 + 3920);
        int o = i / 3, k = i % 3;
        int idx = 32 * k + lane;
        bool bit = (idx < 80) && (fc2[o * 80 + idx] > 0.f);
        uint32_t word = __ballot_sync(0xFFFFFFFFu, bit);
        if (lane == 0) g_FC2[i] = word;
    }
}

// ---------------- kernel A: conv1 + BN1 + sign + bitpack, f32x2 -------------
// 96 threads, 95 active: w = tid%19, slot = tid/19 (5 slots x 12 h rows = 60).
// Channels processed in pairs (c1, c1+20) packed into f32x2 lanes; per-lane
// accumulation is t-ascending rn-FMA, bit-identical to the scalar version.
__global__ __launch_bounds__(96, 4) void ka_conv1(
    const float* __restrict__ x, const float* __restrict__ w1,
    const float* __restrict__ bg, const float* __restrict__ bbv,
    const float* __restrict__ bm, const float* __restrict__ bv) {
    __shared__ float xs[88 * 19];
    __shared__ ull wsp[20 * 29];            // packed sign pairs (c1, c1+20)
    __shared__ float scs[40], sbs[40];
    __shared__ uint32_t outw[60 * 24];

    int tid = threadIdx.x;
    int h0 = blockIdx.x * 60;
    int b = blockIdx.y;

    for (int idx = tid; idx < 88 * 19; idx += 96) {
        int r = idx / 19, c = idx % 19;
        int gh = h0 - 14 + r;
        xs[idx] = (gh >= 0 && gh < 600) ? x[(b * 600 + gh) * 19 + c] : 0.f;
    }
    for (int idx = tid; idx < 20 * 29; idx += 96) {
        int p = idx / 29, t = idx % 29;
        float lo = (w1[p * 29 + t] > 0.f) ? 1.f : -1.f;
        float hi = (w1[(p + 20) * 29 + t] > 0.f) ? 1.f : -1.f;
        wsp[idx] = pk2(lo, hi);
    }
    if (tid < 40) {
        float sc = bg[tid] / sqrtf(bv[tid] + EPS);
        scs[tid] = sc;
        sbs[tid] = __fsub_rn(bbv[tid], __fmul_rn(bm[tid], sc));
    }
    for (int idx = tid; idx < 60 * 24; idx += 96) outw[idx] = 0;
    __syncthreads();

    if (tid < 95) {
        int w = tid % 19;
        int slot = tid / 19;                 // 0..4, 12 h rows each
        ull xd[40];
        #pragma unroll
        for (int i = 0; i < 40; i++) {
            float v = xs[(slot * 12 + i) * 19 + w];
            xd[i] = pk2(v, v);
        }

        ull mask[12];
        #pragma unroll
        for (int j = 0; j < 12; j++) mask[j] = 0ull;

        for (int pair = 0; pair < 20; pair++) {
            ull acc[12];
            #pragma unroll
            for (int j = 0; j < 12; j++) acc[j] = 0ull;   // (+0.f, +0.f)
            #pragma unroll
            for (int t = 0; t < 29; t++) {                // sequential tap order
                ull s2 = wsp[pair * 29 + t];
                #pragma unroll
                for (int j = 0; j < 12; j++) acc[j] = fma2(s2, xd[t + j], acc[j]);
            }
            float sclo = scs[pair], sblo = sbs[pair];
            float schi = scs[pair + 20], sbhi = sbs[pair + 20];
            #pragma unroll
            for (int j = 0; j < 12; j++) {
                float alo, ahi;
                upk2(acc[j], alo, ahi);
                float ylo = __fadd_rn(__fmul_rn(alo, sclo), sblo);
                float yhi = __fadd_rn(__fmul_rn(ahi, schi), sbhi);
                if (ylo > 0.f) mask[j] |= (1ull << pair);
                if (yhi > 0.f) mask[j] |= (1ull << (pair + 20));
            }
        }
        // pack: bits [w*40, w*40+40) span exactly 2 u32 words (w*40 % 32 in {0,8,16,24})
        int b0 = w * 40;
        int wi = b0 >> 5, sh = b0 & 31;
        #pragma unroll
        for (int j = 0; j < 12; j++) {
            int row = slot * 12 + j;
            atomicOr(&outw[row * 24 + wi], (uint32_t)(mask[j] << sh));
            atomicOr(&outw[row * 24 + wi + 1], (uint32_t)(mask[j] >> (32 - sh)));
        }
    }
    __syncthreads();
    for (int idx = tid; idx < 60 * 24; idx += 96) {
        int row = idx / 24, k = idx % 24;
        g_A[((b * 600) + h0 + row) * 24 + k] = outw[idx];
    }
}

// ---------------- kernel B: binary conv2 + BN2 + PReLU + pool + FC1/BN3/FC2 -
// Block per batch. Thread owns h rows: loads the 760-bit row ONCE (12 u64 from
// L2-resident g_A), loops channels with broadcast weight LDS. Two 20-channel
// passes over pbuf. Ends with the fused fully-connected head.
__global__ __launch_bounds__(256) void kb_conv2(
    const float* __restrict__ bg, const float* __restrict__ bbv,
    const float* __restrict__ bm, const float* __restrict__ bv,
    const float* __restrict__ a2,
    const float* __restrict__ g3, const float* __restrict__ b3,
    const float* __restrict__ m3, const float* __restrict__ v3,
    float* __restrict__ out) {
    extern __shared__ uint32_t sm[];
    float*    pbuf = (float*)sm;                  // 20*600 floats   (48000 B)
    uint32_t* w2p  = sm + 12000;                  // 40*24 u32       (3840 B, 8B-aligned)
    uint32_t* fcw  = w2p + 40 * 24;               // 80*49 u32       (15680 B)
    float*    ssc  = (float*)(fcw + 80 * 49);     // 40
    float*    ssb  = ssc + 40;                    // 40
    float*    sc3  = ssb + 40;                    // 80
    float*    sb3  = sc3 + 80;                    // 80
    uint32_t* outm = (uint32_t*)(sb3 + 80);       // 49
    uint32_t* hb   = outm + 52;                   // 3 (8B-aligned region)

    int tid = threadIdx.x;
    int b = blockIdx.x;

    for (int idx = tid; idx < 40 * 24; idx += 256) w2p[idx] = g_W2[idx];
    for (int idx = tid; idx < 80 * 49; idx += 256) fcw[idx] = g_FC1[idx];
    if (tid < 40) {
        float sc = bg[tid] / sqrtf(bv[tid] + EPS);
        ssc[tid] = sc;
        ssb[tid] = __fsub_rn(bbv[tid], __fmul_rn(bm[tid], sc));
    }
    if (tid < 80) {
        float sc = g3[tid] / sqrtf(v3[tid] + EPS);
        sc3[tid] = sc;
        sb3[tid] = __fsub_rn(b3[tid], __fmul_rn(m3[tid], sc));
    }
    if (tid < 52) outm[tid] = 0;
    float av = a2[0];
    __syncthreads();

    const ull* arow_base = (const ull*)(g_A + b * 600 * 24);
    const ull* w2p64 = (const ull*)w2p;

    #pragma unroll
    for (int p = 0; p < 2; p++) {
        for (int h = tid; h < 600; h += 256) {
            ull ab[12];
            const ull* ar = arow_base + h * 12;
            #pragma unroll
            for (int k = 0; k < 12; k++) ab[k] = __ldg(&ar[k]);
            #pragma unroll 4
            for (int c = 0; c < 20; c++) {
                int c2 = p * 20 + c;
                const ull* wr = w2p64 + c2 * 12;
                int cnt = 0;
                #pragma unroll
                for (int k = 0; k < 12; k++) cnt += __popcll(ab[k] ^ wr[k]);
                float dot = (float)(760 - 2 * cnt);                 // exact integer
                float y = __fadd_rn(__fmul_rn(dot, ssc[c2]), ssb[c2]);
                pbuf[c * 600 + h] = (y >= 0.f) ? y : __fmul_rn(av, y);
            }
        }
        __syncthreads();
        // pooling: 20 channels x 39 windows, each summed ascending
        for (int idx = tid; idx < 20 * 39; idx += 256) {
            int c = idx / 39, j = idx % 39;
            const float* pw = pbuf + c * 600 + 15 * j;
            float s = 0.f;
            #pragma unroll 1
            for (int i = 0; i < 30; i++) s = __fadd_rn(s, pw[i]);
            if (s > 0.f) {
                int bit = (p * 20 + c) * 39 + j;                    // flat index in 1560
                atomicOr(&outm[bit >> 5], 1u << (bit & 31));
            }
        }
        __syncthreads();
    }

    // fused FC1 + BN3 + sign + FC2
    bool bit = false;
    if (tid < 80) {
        int cnt = 0;
        #pragma unroll
        for (int k = 0; k < 49; k++) cnt += __popc(outm[k] ^ fcw[tid * 49 + k]);
        int dot = 1560 - 2 * cnt;                                   // exact integer
        float y = __fadd_rn(__fmul_rn((float)dot, sc3[tid]), sb3[tid]);
        bit = (y > 0.f);                                            // sign(prelu(y)) = sign(y)
    }
    uint32_t bl = __ballot_sync(0xFFFFFFFFu, bit);
    if ((tid & 31) == 0 && tid < 96) hb[tid >> 5] = bl;
    __syncthreads();

    if (tid < 2) {
        int cnt = 0;
        #pragma unroll
        for (int k = 0; k < 3; k++) cnt += __popc(hb[k] ^ g_FC2[tid * 3 + k]);
        out[b * 2 + tid] = (float)(80 - 2 * cnt);                   // exact integer
    }
}

// ---------------- launch -----------------------------------------------------
extern "C" void kernel_launch(void* const* d_in, const int* in_sizes, int n_in,
                              void* d_out, int out_size) {
    const float* x    = (const float*)d_in[0];
    const float* w1   = (const float*)d_in[1];
    const float* bn1g = (const float*)d_in[2];
    const float* bn1b = (const float*)d_in[3];
    const float* bn1m = (const float*)d_in[4];
    const float* bn1v = (const float*)d_in[5];
    const float* w2   = (const float*)d_in[7];
    const float* bn2g = (const float*)d_in[8];
    const float* bn2b = (const float*)d_in[9];
    const float* bn2m = (const float*)d_in[10];
    const float* bn2v = (const float*)d_in[11];
    const float* a2   = (const float*)d_in[12];
    const float* fc1  = (const float*)d_in[13];
    const float* bn3g = (const float*)d_in[14];
    const float* bn3b = (const float*)d_in[15];
    const float* bn3m = (const float*)d_in[16];
    const float* bn3v = (const float*)d_in[17];
    const float* fc2  = (const float*)d_in[19];
    float* out = (float*)d_out;

    int nwords = 960 + 3920 + 6;
    int nthreads = nwords * 32;
    kw_pack<<<(nthreads + 255) / 256, 256>>>(w2, fc1, fc2);

    dim3 gA(10, 256);
    ka_conv1<<<gA, 96>>>(x, w1, bn1g, bn1b, bn1m, bn1v);

    size_t smemB = (size_t)(12000 + 40 * 24 + 80 * 49 + 40 + 40 + 80 + 80 + 52 + 4) * 4;
    cudaFuncSetAttribute(kb_conv2, cudaFuncAttributeMaxDynamicSharedMemorySize, (int)smemB);
    kb_conv2<<<256, 256, smemB>>>(bn2g, bn2b, bn2m, bn2v, a2,
                                  bn3g, bn3b, bn3m, bn3v, out);
}